// round 8
// baseline (speedup 1.0000x reference)
#include <cuda_runtime.h>
#include <cuda_bf16.h>
#include <cuda_pipeline.h>
#include <mma.h>
#include <math.h>

using namespace nvcuda;

// Problem constants
#define B_  2
#define S_  2048
#define D_  1024
#define H_  16
#define DK_ 64
#define M_  (B_*S_)

// GEMM v4 tiling: CTA 128x64, BK=16, 4-stage cp.async ring, 8 warps (32x32)
#define BM 128
#define BN 64
#define BK 16
#define LDT 24                         // padded smem row, elements (48B, 16B-aligned)
#define AH_OFF 0
#define AL_OFF (BM*LDT)                // 3072
#define BH_OFF (2*BM*LDT)              // 6144
#define BL_OFF (2*BM*LDT + BN*LDT)     // 7680
#define SE     (2*BM*LDT + 2*BN*LDT)   // 9216 elems per stage
#define NSTAGE 4
#define GEMM_SMEM (NSTAGE*SE*2)        // 73728 bytes -> 2 CTAs/SM

// Scratch (device globals — no allocation allowed)
__device__ float g_Qp[B_*S_*D_];
__device__ float g_Kp[B_*S_*D_];
__device__ float g_Vp[B_*S_*D_];
__device__ float g_O [B_*S_*D_];
__device__ __nv_bfloat16 g_Xh[M_*D_];
__device__ __nv_bfloat16 g_Xl[M_*D_];
__device__ __nv_bfloat16 g_Wh[D_*D_];
__device__ __nv_bfloat16 g_Wl[D_*D_];

// ---------------------------------------------------------------------------
// Merged fp32 -> (hi, lo) bf16 split for X and W in one launch.
// ---------------------------------------------------------------------------
__device__ __forceinline__ void split4(const float4* src, __nv_bfloat16* hi,
                                       __nv_bfloat16* lo, int i)
{
    float4 v = src[i];
    __nv_bfloat16 h0 = __float2bfloat16(v.x);
    __nv_bfloat16 h1 = __float2bfloat16(v.y);
    __nv_bfloat16 h2 = __float2bfloat16(v.z);
    __nv_bfloat16 h3 = __float2bfloat16(v.w);
    __nv_bfloat162 hh0, hh1, ll0, ll1;
    hh0.x = h0; hh0.y = h1; hh1.x = h2; hh1.y = h3;
    ll0.x = __float2bfloat16(v.x - __bfloat162float(h0));
    ll0.y = __float2bfloat16(v.y - __bfloat162float(h1));
    ll1.x = __float2bfloat16(v.z - __bfloat162float(h2));
    ll1.y = __float2bfloat16(v.w - __bfloat162float(h3));
    *(__nv_bfloat162*)&hi[i*4]     = hh0;
    *(__nv_bfloat162*)&hi[i*4 + 2] = hh1;
    *(__nv_bfloat162*)&lo[i*4]     = ll0;
    *(__nv_bfloat162*)&lo[i*4 + 2] = ll1;
}

__global__ __launch_bounds__(256)
void cvt_merged_kernel(const float4* __restrict__ x,
                       __nv_bfloat16* __restrict__ xh,
                       __nv_bfloat16* __restrict__ xl,
                       int nx4,
                       const float4* __restrict__ w,
                       __nv_bfloat16* __restrict__ wh,
                       __nv_bfloat16* __restrict__ wl,
                       int nw4)
{
    int i = blockIdx.x * blockDim.x + threadIdx.x;
    if (i < nx4) {
        split4(x, xh, xl, i);
    } else if (i < nx4 + nw4) {
        split4(w, wh, wl, i - nx4);
    }
}

// ---------------------------------------------------------------------------
// GEMM v4: Y[M,N] = X[M,K] @ W[N,K]^T + bias[N], bf16 hi/lo 3-pass.
// 4-stage ring, ONE sync per K-slab, low regs/smem -> 2 CTAs/SM.
// ---------------------------------------------------------------------------
__device__ __forceinline__ void gemm_issue_tile(
    __nv_bfloat16* sm, int stage,
    const __nv_bfloat16* Xh, const __nv_bfloat16* Xl,
    const __nv_bfloat16* Wh, const __nv_bfloat16* Wl,
    int m0, int n0, int k0, int K, int tid)
{
    __nv_bfloat16* sb = sm + stage * SE;
    // 768 16B-chunks per stage: A hi 256, A lo 256, B hi 128, B lo 128.
    for (int p = 0; p < 3; p++) {
        int g = tid + p * 256;               // 0..767
        if (g < 512) {                       // A region
            int hsel = g >> 8;               // 0 hi, 1 lo
            int ci   = g & 255;
            int row  = ci >> 1;              // 0..127
            int cc   = ci & 1;               // 16B chunk within row
            const __nv_bfloat16* src =
                (hsel ? Xl : Xh) + (size_t)(m0 + row) * K + k0 + cc * 8;
            __pipeline_memcpy_async(sb + hsel * AL_OFF + row * LDT + cc * 8, src, 16);
        } else {                             // B region
            int g2   = g - 512;              // 0..255
            int hsel = g2 >> 7;
            int ci   = g2 & 127;
            int row  = ci >> 1;              // 0..63
            int cc   = ci & 1;
            const __nv_bfloat16* src =
                (hsel ? Wl : Wh) + (size_t)(n0 + row) * K + k0 + cc * 8;
            __pipeline_memcpy_async(sb + BH_OFF + hsel * (BN * LDT) + row * LDT + cc * 8,
                                    src, 16);
        }
    }
}

__global__ __launch_bounds__(256)
void gemm_wmma_kernel(const __nv_bfloat16* __restrict__ Xh,
                      const __nv_bfloat16* __restrict__ Xl,
                      const __nv_bfloat16* __restrict__ Wh,
                      const __nv_bfloat16* __restrict__ Wl,
                      const float* __restrict__ bias,
                      float* __restrict__ Y,
                      int M, int N, int K)
{
    extern __shared__ __nv_bfloat16 sm[];
    __shared__ __align__(16) float biasTile[16][72];

    const int tid = threadIdx.x;
    const int wid = tid >> 5;
    const int m0  = blockIdx.y * BM;
    const int n0  = blockIdx.x * BN;
    const int wm  = (wid & 3) * 32;    // 4 warps in M
    const int wn  = (wid >> 2) * 32;   // 2 warps in N

    for (int idx = tid; idx < 16 * 64; idx += 256) {
        int r = idx >> 6;
        int c = idx & 63;
        biasTile[r][c] = bias[n0 + c];
    }
    __syncthreads();

    wmma::fragment<wmma::accumulator, 16, 16, 16, float> acc[2][2];
    for (int mi = 0; mi < 2; mi++)
        for (int ni = 0; ni < 2; ni++)
            wmma::load_matrix_sync(acc[mi][ni], &biasTile[0][wn + ni * 16], 72,
                                   wmma::mem_row_major);

    const int NT = K / BK;   // 64

    gemm_issue_tile(sm, 0, Xh, Xl, Wh, Wl, m0, n0, 0, K, tid);
    __pipeline_commit();
    gemm_issue_tile(sm, 1, Xh, Xl, Wh, Wl, m0, n0, BK, K, tid);
    __pipeline_commit();
    gemm_issue_tile(sm, 2, Xh, Xl, Wh, Wl, m0, n0, 2 * BK, K, tid);
    __pipeline_commit();

    for (int t = 0; t < NT; t++) {
        __pipeline_wait_prior(2);      // tile t resident
        __syncthreads();               // all threads done with tile t-1
        if (t + 3 < NT)
            gemm_issue_tile(sm, (t + 3) % NSTAGE, Xh, Xl, Wh, Wl, m0, n0,
                            (t + 3) * BK, K, tid);
        __pipeline_commit();           // keep group count uniform

        const __nv_bfloat16* sb = sm + (t % NSTAGE) * SE;
        wmma::fragment<wmma::matrix_b, 16, 16, 16, __nv_bfloat16, wmma::col_major> bh[2], bl[2];
        for (int ni = 0; ni < 2; ni++) {
            int r = wn + ni * 16;
            wmma::load_matrix_sync(bh[ni], sb + BH_OFF + r * LDT, LDT);
            wmma::load_matrix_sync(bl[ni], sb + BL_OFF + r * LDT, LDT);
        }
        for (int mi = 0; mi < 2; mi++) {
            wmma::fragment<wmma::matrix_a, 16, 16, 16, __nv_bfloat16, wmma::row_major> ah, al;
            int r = wm + mi * 16;
            wmma::load_matrix_sync(ah, sb + AH_OFF + r * LDT, LDT);
            wmma::load_matrix_sync(al, sb + AL_OFF + r * LDT, LDT);
            for (int ni = 0; ni < 2; ni++) {
                wmma::mma_sync(acc[mi][ni], ah, bh[ni], acc[mi][ni]);
                wmma::mma_sync(acc[mi][ni], ah, bl[ni], acc[mi][ni]);
                wmma::mma_sync(acc[mi][ni], al, bh[ni], acc[mi][ni]);
            }
        }
    }

    for (int mi = 0; mi < 2; mi++) {
        for (int ni = 0; ni < 2; ni++) {
            int row = m0 + wm + mi * 16;
            int col = n0 + wn + ni * 16;
            wmma::store_matrix_sync(&Y[(size_t)row * N + col], acc[mi][ni], N,
                                    wmma::mem_row_major);
        }
    }
}

// ---------------------------------------------------------------------------
// Flash attention (causal), fp32 — exact R6 v2 (best-known): 256 thr/CTA,
// 2 threads per query, shfl-combined scores, static smem.
// ---------------------------------------------------------------------------
__global__ __launch_bounds__(256)
void flash_attn_kernel(const float* __restrict__ Qp,
                       const float* __restrict__ Kp,
                       const float* __restrict__ Vp,
                       float* __restrict__ O)
{
    __shared__ float Ks[64][64];
    __shared__ float Vs[64][64];

    const int tid   = threadIdx.x;
    const int t     = tid >> 1;
    const int half  = tid & 1;
    const int qtile = blockIdx.x;
    const int bh    = blockIdx.y;
    const int b     = bh / H_;
    const int h     = bh % H_;
    const int qi    = qtile * 128 + t;
    const int hoff  = half * 32;

    const float* qrow = &Qp[((size_t)b * S_ + qi) * D_ + h * DK_ + hoff];
    float q[32];
#pragma unroll
    for (int d4 = 0; d4 < 8; d4++) {
        float4 v = *(const float4*)&qrow[d4 * 4];
        q[d4*4+0] = v.x; q[d4*4+1] = v.y; q[d4*4+2] = v.z; q[d4*4+3] = v.w;
    }

    float acc[32];
#pragma unroll
    for (int d = 0; d < 32; d++) acc[d] = 0.f;
    float m = -INFINITY;
    float l = 0.f;

    const int ntiles = qtile * 2 + 2;
    for (int kt = 0; kt < ntiles; kt++) {
        const int kb = kt * 64;
#pragma unroll
        for (int p = 0; p < 4; p++) {
            int idx = tid + p * 256;
            int r   = idx >> 4;
            int c   = idx & 15;
            size_t g = ((size_t)b * S_ + kb + r) * D_ + h * DK_ + c * 4;
            *(float4*)&Ks[r][c * 4] = *(const float4*)&Kp[g];
            *(float4*)&Vs[r][c * 4] = *(const float4*)&Vp[g];
        }
        __syncthreads();

        for (int j0 = 0; j0 < 64; j0 += 8) {
            float s[8];
#pragma unroll
            for (int jj = 0; jj < 8; jj++) {
                float sj = 0.f;
#pragma unroll
                for (int d4 = 0; d4 < 8; d4++) {
                    float4 kv = *(const float4*)&Ks[j0 + jj][hoff + d4 * 4];
                    sj = fmaf(q[d4*4+0], kv.x, sj);
                    sj = fmaf(q[d4*4+1], kv.y, sj);
                    sj = fmaf(q[d4*4+2], kv.z, sj);
                    sj = fmaf(q[d4*4+3], kv.w, sj);
                }
                sj += __shfl_xor_sync(0xffffffffu, sj, 1);
                int kj = kb + j0 + jj;
                s[jj] = (kj <= qi) ? sj * 0.125f : -1e9f;
            }
            float mt = m;
#pragma unroll
            for (int jj = 0; jj < 8; jj++) mt = fmaxf(mt, s[jj]);
            float scale = __expf(m - mt);
            float p[8];
            float ls = 0.f;
#pragma unroll
            for (int jj = 0; jj < 8; jj++) {
                p[jj] = __expf(s[jj] - mt);
                ls += p[jj];
            }
            l = l * scale + ls;
            m = mt;
#pragma unroll
            for (int d = 0; d < 32; d++) acc[d] *= scale;
#pragma unroll
            for (int jj = 0; jj < 8; jj++) {
                float pj = p[jj];
#pragma unroll
                for (int d4 = 0; d4 < 8; d4++) {
                    float4 vv = *(const float4*)&Vs[j0 + jj][hoff + d4 * 4];
                    acc[d4*4+0] = fmaf(pj, vv.x, acc[d4*4+0]);
                    acc[d4*4+1] = fmaf(pj, vv.y, acc[d4*4+1]);
                    acc[d4*4+2] = fmaf(pj, vv.z, acc[d4*4+2]);
                    acc[d4*4+3] = fmaf(pj, vv.w, acc[d4*4+3]);
                }
            }
        }
        __syncthreads();
    }

    const float inv = 1.f / l;
    float* orow = &O[((size_t)b * S_ + qi) * D_ + h * DK_ + hoff];
#pragma unroll
    for (int d4 = 0; d4 < 8; d4++) {
        float4 o;
        o.x = acc[d4*4+0] * inv;
        o.y = acc[d4*4+1] * inv;
        o.z = acc[d4*4+2] * inv;
        o.w = acc[d4*4+3] * inv;
        *(float4*)&orow[d4 * 4] = o;
    }
}

// ---------------------------------------------------------------------------
// Launch. Inputs: q,k,v,mask,Wq,bq,Wk,bk,Wv,bv,Wo,bo
// ---------------------------------------------------------------------------
extern "C" void kernel_launch(void* const* d_in, const int* in_sizes, int n_in,
                              void* d_out, int out_size)
{
    const float* q    = (const float*)d_in[0];
    const float* k    = (const float*)d_in[1];
    const float* v    = (const float*)d_in[2];
    const float* Wq   = (const float*)d_in[4];
    const float* bq   = (const float*)d_in[5];
    const float* Wk   = (const float*)d_in[6];
    const float* bk   = (const float*)d_in[7];
    const float* Wv   = (const float*)d_in[8];
    const float* bv   = (const float*)d_in[9];
    const float* Wo   = (const float*)d_in[10];
    const float* bo   = (const float*)d_in[11];
    float* out = (float*)d_out;

    float *Qp;
    float *Kp;
    float *Vp;
    float *O;
    __nv_bfloat16 *Xh;
    __nv_bfloat16 *Xl;
    __nv_bfloat16 *Wh;
    __nv_bfloat16 *Wl;
    cudaGetSymbolAddress((void**)&Qp, g_Qp);
    cudaGetSymbolAddress((void**)&Kp, g_Kp);
    cudaGetSymbolAddress((void**)&Vp, g_Vp);
    cudaGetSymbolAddress((void**)&O,  g_O);
    cudaGetSymbolAddress((void**)&Xh, g_Xh);
    cudaGetSymbolAddress((void**)&Xl, g_Xl);
    cudaGetSymbolAddress((void**)&Wh, g_Wh);
    cudaGetSymbolAddress((void**)&Wl, g_Wl);

    cudaFuncSetAttribute(gemm_wmma_kernel,
                         cudaFuncAttributeMaxDynamicSharedMemorySize, GEMM_SMEM);

    const int nX4 = M_ * D_ / 4;
    const int nW4 = D_ * D_ / 4;
    dim3 cvtg((nX4 + nW4 + 255) / 256);
    dim3 ggrid(D_ / BN, M_ / BM);   // (16, 32)

    // Q projection
    cvt_merged_kernel<<<cvtg, 256>>>((const float4*)q, Xh, Xl, nX4,
                                     (const float4*)Wq, Wh, Wl, nW4);
    gemm_wmma_kernel<<<ggrid, 256, GEMM_SMEM>>>(Xh, Xl, Wh, Wl, bq, Qp, M_, D_, D_);
    // K projection
    cvt_merged_kernel<<<cvtg, 256>>>((const float4*)k, Xh, Xl, nX4,
                                     (const float4*)Wk, Wh, Wl, nW4);
    gemm_wmma_kernel<<<ggrid, 256, GEMM_SMEM>>>(Xh, Xl, Wh, Wl, bk, Kp, M_, D_, D_);
    // V projection
    cvt_merged_kernel<<<cvtg, 256>>>((const float4*)v, Xh, Xl, nX4,
                                     (const float4*)Wv, Wh, Wl, nW4);
    gemm_wmma_kernel<<<ggrid, 256, GEMM_SMEM>>>(Xh, Xl, Wh, Wl, bv, Vp, M_, D_, D_);

    // Attention
    dim3 fgrid(S_ / 128, B_ * H_);
    flash_attn_kernel<<<fgrid, 256>>>(Qp, Kp, Vp, O);

    // Output projection
    cvt_merged_kernel<<<cvtg, 256>>>((const float4*)O, Xh, Xl, nX4,
                                     (const float4*)Wo, Wh, Wl, nW4);
    gemm_wmma_kernel<<<ggrid, 256, GEMM_SMEM>>>(Xh, Xl, Wh, Wl, bo, out, M_, D_, D_);
}

// round 9
// speedup vs baseline: 1.1365x; 1.1365x over previous
#include <cuda_runtime.h>
#include <cuda_bf16.h>
#include <cuda_pipeline.h>
#include <mma.h>
#include <math.h>

using namespace nvcuda;

// Problem constants
#define B_  2
#define S_  2048
#define D_  1024
#define H_  16
#define DK_ 64
#define M_  (B_*S_)

// GEMM v2 tiling (R6 measured-best: ~80us per GEMM)
#define BM 128
#define BN 128
#define BK 32
#define LDT 40                    // padded smem row (elements); 80B stride
#define TILE_ELEMS (BM*LDT)       // 5120 elements per tile
#define STAGE_ELEMS (4*TILE_ELEMS)// Ah, Al, Bh, Bl
#define SMEM_BYTES (2*STAGE_ELEMS*2)

// Scratch (device globals — no allocation allowed)
__device__ float g_Qp[B_*S_*D_];
__device__ float g_Kp[B_*S_*D_];
__device__ float g_Vp[B_*S_*D_];
__device__ float g_O [B_*S_*D_];
__device__ __nv_bfloat16 g_Xh[M_*D_];
__device__ __nv_bfloat16 g_Xl[M_*D_];
__device__ __nv_bfloat16 g_Wh[D_*D_];
__device__ __nv_bfloat16 g_Wl[D_*D_];

// ---------------------------------------------------------------------------
// Merged fp32 -> (hi, lo) bf16 split for X and W in one launch.
// ---------------------------------------------------------------------------
__device__ __forceinline__ void split4(const float4* src, __nv_bfloat16* hi,
                                       __nv_bfloat16* lo, int i)
{
    float4 v = src[i];
    __nv_bfloat16 h0 = __float2bfloat16(v.x);
    __nv_bfloat16 h1 = __float2bfloat16(v.y);
    __nv_bfloat16 h2 = __float2bfloat16(v.z);
    __nv_bfloat16 h3 = __float2bfloat16(v.w);
    __nv_bfloat162 hh0, hh1, ll0, ll1;
    hh0.x = h0; hh0.y = h1; hh1.x = h2; hh1.y = h3;
    ll0.x = __float2bfloat16(v.x - __bfloat162float(h0));
    ll0.y = __float2bfloat16(v.y - __bfloat162float(h1));
    ll1.x = __float2bfloat16(v.z - __bfloat162float(h2));
    ll1.y = __float2bfloat16(v.w - __bfloat162float(h3));
    *(__nv_bfloat162*)&hi[i*4]     = hh0;
    *(__nv_bfloat162*)&hi[i*4 + 2] = hh1;
    *(__nv_bfloat162*)&lo[i*4]     = ll0;
    *(__nv_bfloat162*)&lo[i*4 + 2] = ll1;
}

__global__ __launch_bounds__(256)
void cvt_merged_kernel(const float4* __restrict__ x,
                       __nv_bfloat16* __restrict__ xh,
                       __nv_bfloat16* __restrict__ xl,
                       int nx4,
                       const float4* __restrict__ w,
                       __nv_bfloat16* __restrict__ wh,
                       __nv_bfloat16* __restrict__ wl,
                       int nw4)
{
    int i = blockIdx.x * blockDim.x + threadIdx.x;
    if (i < nx4) {
        split4(x, xh, xl, i);
    } else if (i < nx4 + nw4) {
        split4(w, wh, wl, i - nx4);
    }
}

// ---------------------------------------------------------------------------
// GEMM v2 (R6 exact): Y[M,N] = X[M,K] @ W[N,K]^T + bias[N].
// CTA 128x128, BK=32 double-buffered dynamic smem (80KB), 8 warps,
// warp tile 64x32 -> 48 mma per 24 fragment loads per main-loop iteration.
// ---------------------------------------------------------------------------
__global__ __launch_bounds__(256)
void gemm_wmma_kernel(const __nv_bfloat16* __restrict__ Xh,
                      const __nv_bfloat16* __restrict__ Xl,
                      const __nv_bfloat16* __restrict__ Wh,
                      const __nv_bfloat16* __restrict__ Wl,
                      const float* __restrict__ bias,
                      float* __restrict__ Y,
                      int M, int N, int K)
{
    extern __shared__ __nv_bfloat16 sm[];
    __shared__ __align__(16) float biasTile[16][136];

    const int tid = threadIdx.x;
    const int wid = tid >> 5;
    const int m0  = blockIdx.y * BM;
    const int n0  = blockIdx.x * BN;
    const int wm  = (wid & 1) * 64;    // warp M offset (2 warps in M)
    const int wn  = (wid >> 1) * 32;   // warp N offset (4 warps in N)

    for (int idx = tid; idx < 16 * 128; idx += 256) {
        int r = idx >> 7;
        int c = idx & 127;
        biasTile[r][c] = bias[n0 + c];
    }
    __syncthreads();

    wmma::fragment<wmma::accumulator, 16, 16, 16, float> acc[4][2];
    for (int mi = 0; mi < 4; mi++)
        for (int ni = 0; ni < 2; ni++)
            wmma::load_matrix_sync(acc[mi][ni], &biasTile[0][wn + ni * 16], 136,
                                   wmma::mem_row_major);

    const int NT = K / BK;   // 32

    // Prologue: prefetch tile 0 into stage 0 (each thread: 8 x 16B)
    {
        for (int p = 0; p < 2; p++) {
            int chunk = tid + p * 256;       // 0..511
            int row = chunk >> 2;
            int cc  = chunk & 3;
            const __nv_bfloat16* sa = Xh + (size_t)(m0 + row) * K + cc * 8;
            const __nv_bfloat16* sb = Xl + (size_t)(m0 + row) * K + cc * 8;
            const __nv_bfloat16* sc = Wh + (size_t)(n0 + row) * K + cc * 8;
            const __nv_bfloat16* sd = Wl + (size_t)(n0 + row) * K + cc * 8;
            int so = row * LDT + cc * 8;
            __pipeline_memcpy_async(&sm[so], sa, 16);
            __pipeline_memcpy_async(&sm[TILE_ELEMS + so], sb, 16);
            __pipeline_memcpy_async(&sm[2 * TILE_ELEMS + so], sc, 16);
            __pipeline_memcpy_async(&sm[3 * TILE_ELEMS + so], sd, 16);
        }
        __pipeline_commit();
    }

    for (int t = 0; t < NT; t++) {
        int st = (t & 1) * STAGE_ELEMS;
        if (t + 1 < NT) {
            int k0 = (t + 1) * BK;
            int sn = ((t + 1) & 1) * STAGE_ELEMS;
            for (int p = 0; p < 2; p++) {
                int chunk = tid + p * 256;
                int row = chunk >> 2;
                int cc  = chunk & 3;
                const __nv_bfloat16* sa = Xh + (size_t)(m0 + row) * K + k0 + cc * 8;
                const __nv_bfloat16* sb = Xl + (size_t)(m0 + row) * K + k0 + cc * 8;
                const __nv_bfloat16* sc = Wh + (size_t)(n0 + row) * K + k0 + cc * 8;
                const __nv_bfloat16* sd = Wl + (size_t)(n0 + row) * K + k0 + cc * 8;
                int so = row * LDT + cc * 8;
                __pipeline_memcpy_async(&sm[sn + so], sa, 16);
                __pipeline_memcpy_async(&sm[sn + TILE_ELEMS + so], sb, 16);
                __pipeline_memcpy_async(&sm[sn + 2 * TILE_ELEMS + so], sc, 16);
                __pipeline_memcpy_async(&sm[sn + 3 * TILE_ELEMS + so], sd, 16);
            }
            __pipeline_commit();
            __pipeline_wait_prior(1);
        } else {
            __pipeline_wait_prior(0);
        }
        __syncthreads();

        for (int ks = 0; ks < 2; ks++) {
            int kc = ks * 16;
            wmma::fragment<wmma::matrix_a, 16, 16, 16, __nv_bfloat16, wmma::row_major> ah[4], al[4];
            wmma::fragment<wmma::matrix_b, 16, 16, 16, __nv_bfloat16, wmma::col_major> bh[2], bl[2];
            for (int mi = 0; mi < 4; mi++) {
                int r = wm + mi * 16;
                wmma::load_matrix_sync(ah[mi], &sm[st + r * LDT + kc], LDT);
                wmma::load_matrix_sync(al[mi], &sm[st + TILE_ELEMS + r * LDT + kc], LDT);
            }
            for (int ni = 0; ni < 2; ni++) {
                int r = wn + ni * 16;
                wmma::load_matrix_sync(bh[ni], &sm[st + 2 * TILE_ELEMS + r * LDT + kc], LDT);
                wmma::load_matrix_sync(bl[ni], &sm[st + 3 * TILE_ELEMS + r * LDT + kc], LDT);
            }
            for (int mi = 0; mi < 4; mi++) {
                for (int ni = 0; ni < 2; ni++) {
                    wmma::mma_sync(acc[mi][ni], ah[mi], bh[ni], acc[mi][ni]);
                    wmma::mma_sync(acc[mi][ni], ah[mi], bl[ni], acc[mi][ni]);
                    wmma::mma_sync(acc[mi][ni], al[mi], bh[ni], acc[mi][ni]);
                }
            }
        }
        __syncthreads();
    }

    for (int mi = 0; mi < 4; mi++) {
        for (int ni = 0; ni < 2; ni++) {
            int row = m0 + wm + mi * 16;
            int col = n0 + wn + ni * 16;
            wmma::store_matrix_sync(&Y[(size_t)row * N + col], acc[mi][ni], N,
                                    wmma::mem_row_major);
        }
    }
}

// ---------------------------------------------------------------------------
// Flash attention v1 (R4 exact, measured-best ~700us): causal, fp32,
// 128 threads/CTA, one query row per thread, K/V tiles of 64 in smem.
// ---------------------------------------------------------------------------
__global__ __launch_bounds__(128)
void flash_attn_kernel(const float* __restrict__ Qp,
                       const float* __restrict__ Kp,
                       const float* __restrict__ Vp,
                       float* __restrict__ O)
{
    __shared__ float Ks[64][64];
    __shared__ float Vs[64][64];

    const int t     = threadIdx.x;
    const int qtile = blockIdx.x;
    const int bh    = blockIdx.y;
    const int b     = bh / H_;
    const int h     = bh % H_;
    const int qi    = qtile * 128 + t;

    const float* qrow = &Qp[((size_t)b * S_ + qi) * D_ + h * DK_];
    float q[64];
#pragma unroll
    for (int d4 = 0; d4 < 16; d4++) {
        float4 v = *(const float4*)&qrow[d4 * 4];
        q[d4*4+0] = v.x; q[d4*4+1] = v.y; q[d4*4+2] = v.z; q[d4*4+3] = v.w;
    }

    float acc[64];
#pragma unroll
    for (int d = 0; d < 64; d++) acc[d] = 0.f;
    float m = -INFINITY;
    float l = 0.f;

    const int ntiles = qtile * 2 + 2;
    for (int kt = 0; kt < ntiles; kt++) {
        const int kb = kt * 64;
#pragma unroll
        for (int p = 0; p < 8; p++) {
            int idx = t + p * 128;
            int r   = idx >> 4;
            int c   = idx & 15;
            size_t g = ((size_t)b * S_ + kb + r) * D_ + h * DK_ + c * 4;
            *(float4*)&Ks[r][c * 4] = *(const float4*)&Kp[g];
            *(float4*)&Vs[r][c * 4] = *(const float4*)&Vp[g];
        }
        __syncthreads();

        for (int j0 = 0; j0 < 64; j0 += 8) {
            float s[8];
#pragma unroll
            for (int jj = 0; jj < 8; jj++) {
                float sj = 0.f;
#pragma unroll
                for (int d4 = 0; d4 < 16; d4++) {
                    float4 kv = *(const float4*)&Ks[j0 + jj][d4 * 4];
                    sj = fmaf(q[d4*4+0], kv.x, sj);
                    sj = fmaf(q[d4*4+1], kv.y, sj);
                    sj = fmaf(q[d4*4+2], kv.z, sj);
                    sj = fmaf(q[d4*4+3], kv.w, sj);
                }
                int kj = kb + j0 + jj;
                s[jj] = (kj <= qi) ? sj * 0.125f : -1e9f;
            }
            float mt = m;
#pragma unroll
            for (int jj = 0; jj < 8; jj++) mt = fmaxf(mt, s[jj]);
            float scale = __expf(m - mt);
            float p[8];
            float ls = 0.f;
#pragma unroll
            for (int jj = 0; jj < 8; jj++) {
                p[jj] = __expf(s[jj] - mt);
                ls += p[jj];
            }
            l = l * scale + ls;
            m = mt;
#pragma unroll
            for (int d = 0; d < 64; d++) acc[d] *= scale;
#pragma unroll
            for (int jj = 0; jj < 8; jj++) {
                float pj = p[jj];
#pragma unroll
                for (int d4 = 0; d4 < 16; d4++) {
                    float4 vv = *(const float4*)&Vs[j0 + jj][d4 * 4];
                    acc[d4*4+0] = fmaf(pj, vv.x, acc[d4*4+0]);
                    acc[d4*4+1] = fmaf(pj, vv.y, acc[d4*4+1]);
                    acc[d4*4+2] = fmaf(pj, vv.z, acc[d4*4+2]);
                    acc[d4*4+3] = fmaf(pj, vv.w, acc[d4*4+3]);
                }
            }
        }
        __syncthreads();
    }

    const float inv = 1.f / l;
    float* orow = &O[((size_t)b * S_ + qi) * D_ + h * DK_];
#pragma unroll
    for (int d4 = 0; d4 < 16; d4++) {
        float4 o;
        o.x = acc[d4*4+0] * inv;
        o.y = acc[d4*4+1] * inv;
        o.z = acc[d4*4+2] * inv;
        o.w = acc[d4*4+3] * inv;
        *(float4*)&orow[d4 * 4] = o;
    }
}

// ---------------------------------------------------------------------------
// Launch. Inputs: q,k,v,mask,Wq,bq,Wk,bk,Wv,bv,Wo,bo
// ---------------------------------------------------------------------------
extern "C" void kernel_launch(void* const* d_in, const int* in_sizes, int n_in,
                              void* d_out, int out_size)
{
    const float* q    = (const float*)d_in[0];
    const float* k    = (const float*)d_in[1];
    const float* v    = (const float*)d_in[2];
    const float* Wq   = (const float*)d_in[4];
    const float* bq   = (const float*)d_in[5];
    const float* Wk   = (const float*)d_in[6];
    const float* bk   = (const float*)d_in[7];
    const float* Wv   = (const float*)d_in[8];
    const float* bv   = (const float*)d_in[9];
    const float* Wo   = (const float*)d_in[10];
    const float* bo   = (const float*)d_in[11];
    float* out = (float*)d_out;

    float *Qp;
    float *Kp;
    float *Vp;
    float *O;
    __nv_bfloat16 *Xh;
    __nv_bfloat16 *Xl;
    __nv_bfloat16 *Wh;
    __nv_bfloat16 *Wl;
    cudaGetSymbolAddress((void**)&Qp, g_Qp);
    cudaGetSymbolAddress((void**)&Kp, g_Kp);
    cudaGetSymbolAddress((void**)&Vp, g_Vp);
    cudaGetSymbolAddress((void**)&O,  g_O);
    cudaGetSymbolAddress((void**)&Xh, g_Xh);
    cudaGetSymbolAddress((void**)&Xl, g_Xl);
    cudaGetSymbolAddress((void**)&Wh, g_Wh);
    cudaGetSymbolAddress((void**)&Wl, g_Wl);

    cudaFuncSetAttribute(gemm_wmma_kernel,
                         cudaFuncAttributeMaxDynamicSharedMemorySize, SMEM_BYTES);

    const int nX4 = M_ * D_ / 4;
    const int nW4 = D_ * D_ / 4;
    dim3 cvtg((nX4 + nW4 + 255) / 256);
    dim3 ggrid(D_ / BN, M_ / BM);   // (8, 32)

    // Q projection
    cvt_merged_kernel<<<cvtg, 256>>>((const float4*)q, Xh, Xl, nX4,
                                     (const float4*)Wq, Wh, Wl, nW4);
    gemm_wmma_kernel<<<ggrid, 256, SMEM_BYTES>>>(Xh, Xl, Wh, Wl, bq, Qp, M_, D_, D_);
    // K projection
    cvt_merged_kernel<<<cvtg, 256>>>((const float4*)k, Xh, Xl, nX4,
                                     (const float4*)Wk, Wh, Wl, nW4);
    gemm_wmma_kernel<<<ggrid, 256, SMEM_BYTES>>>(Xh, Xl, Wh, Wl, bk, Kp, M_, D_, D_);
    // V projection
    cvt_merged_kernel<<<cvtg, 256>>>((const float4*)v, Xh, Xl, nX4,
                                     (const float4*)Wv, Wh, Wl, nW4);
    gemm_wmma_kernel<<<ggrid, 256, SMEM_BYTES>>>(Xh, Xl, Wh, Wl, bv, Vp, M_, D_, D_);

    // Attention
    dim3 fgrid(S_ / 128, B_ * H_);
    flash_attn_kernel<<<fgrid, 128>>>(Qp, Kp, Vp, O);

    // Output projection
    cvt_merged_kernel<<<cvtg, 256>>>((const float4*)O, Xh, Xl, nX4,
                                     (const float4*)Wo, Wh, Wl, nW4);
    gemm_wmma_kernel<<<ggrid, 256, SMEM_BYTES>>>(Xh, Xl, Wh, Wl, bo, out, M_, D_, D_);
}

// round 10
// speedup vs baseline: 2.4017x; 2.1132x over previous
#include <cuda_runtime.h>
#include <cuda_bf16.h>
#include <cuda_pipeline.h>
#include <mma.h>
#include <math.h>

using namespace nvcuda;

// Problem constants
#define B_  2
#define S_  2048
#define D_  1024
#define H_  16
#define DK_ 64
#define M_  (B_*S_)

// GEMM v2 tiling (measured ~104us per GEMM)
#define BM 128
#define BN 128
#define BK 32
#define LDT 40
#define TILE_ELEMS (BM*LDT)
#define STAGE_ELEMS (4*TILE_ELEMS)
#define SMEM_BYTES (2*STAGE_ELEMS*2)

// Flash wmma smem layout (bytes). bf16 tiles: 64 rows x 72-elem stride (144B).
#define FQH 0
#define FQL 9216
#define FKV0 18432
#define FKV1 55296
#define FKVSZ 36864
#define FS  92160
#define FPH 110592
#define FPL 119808
#define FOT 129024
#define FOA 147456
#define FST 164864
#define FLASH_SMEM 165632

// Scratch (device globals — no allocation allowed)
__device__ float g_Qp[B_*S_*D_];
__device__ float g_Kp[B_*S_*D_];
__device__ float g_Vp[B_*S_*D_];
__device__ float g_O [B_*S_*D_];
__device__ __nv_bfloat16 g_Xh[M_*D_];
__device__ __nv_bfloat16 g_Xl[M_*D_];
__device__ __nv_bfloat16 g_Wh[D_*D_];
__device__ __nv_bfloat16 g_Wl[D_*D_];
__device__ __nv_bfloat16 g_Qh[M_*D_];
__device__ __nv_bfloat16 g_Ql[M_*D_];
__device__ __nv_bfloat16 g_Kh[M_*D_];
__device__ __nv_bfloat16 g_Kl[M_*D_];
__device__ __nv_bfloat16 g_Vh[M_*D_];
__device__ __nv_bfloat16 g_Vl[M_*D_];

// ---------------------------------------------------------------------------
// fp32 -> (hi, lo) bf16 split helpers.
// ---------------------------------------------------------------------------
__device__ __forceinline__ void split4(const float4* src, __nv_bfloat16* hi,
                                       __nv_bfloat16* lo, int i)
{
    float4 v = src[i];
    __nv_bfloat16 h0 = __float2bfloat16(v.x);
    __nv_bfloat16 h1 = __float2bfloat16(v.y);
    __nv_bfloat16 h2 = __float2bfloat16(v.z);
    __nv_bfloat16 h3 = __float2bfloat16(v.w);
    __nv_bfloat162 hh0, hh1, ll0, ll1;
    hh0.x = h0; hh0.y = h1; hh1.x = h2; hh1.y = h3;
    ll0.x = __float2bfloat16(v.x - __bfloat162float(h0));
    ll0.y = __float2bfloat16(v.y - __bfloat162float(h1));
    ll1.x = __float2bfloat16(v.z - __bfloat162float(h2));
    ll1.y = __float2bfloat16(v.w - __bfloat162float(h3));
    *(__nv_bfloat162*)&hi[i*4]     = hh0;
    *(__nv_bfloat162*)&hi[i*4 + 2] = hh1;
    *(__nv_bfloat162*)&lo[i*4]     = ll0;
    *(__nv_bfloat162*)&lo[i*4 + 2] = ll1;
}

__global__ __launch_bounds__(256)
void cvt_merged_kernel(const float4* __restrict__ x,
                       __nv_bfloat16* __restrict__ xh,
                       __nv_bfloat16* __restrict__ xl,
                       int nx4,
                       const float4* __restrict__ w,
                       __nv_bfloat16* __restrict__ wh,
                       __nv_bfloat16* __restrict__ wl,
                       int nw4)
{
    int i = blockIdx.x * blockDim.x + threadIdx.x;
    if (i < nx4) {
        split4(x, xh, xl, i);
    } else if (i < nx4 + nw4) {
        split4(w, wh, wl, i - nx4);
    }
}

__global__ __launch_bounds__(256)
void cvt3_kernel(const float4* __restrict__ a, __nv_bfloat16* ah, __nv_bfloat16* al,
                 const float4* __restrict__ b2, __nv_bfloat16* bh, __nv_bfloat16* bl,
                 const float4* __restrict__ c, __nv_bfloat16* ch, __nv_bfloat16* cl,
                 int n4)
{
    int i = blockIdx.x * blockDim.x + threadIdx.x;
    if (i < n4) {
        split4(a, ah, al, i);
    } else if (i < 2 * n4) {
        split4(b2, bh, bl, i - n4);
    } else if (i < 3 * n4) {
        split4(c, ch, cl, i - 2 * n4);
    }
}

// ---------------------------------------------------------------------------
// GEMM v2 (measured-best): Y[M,N] = X[M,K] @ W[N,K]^T + bias[N].
// ---------------------------------------------------------------------------
__global__ __launch_bounds__(256)
void gemm_wmma_kernel(const __nv_bfloat16* __restrict__ Xh,
                      const __nv_bfloat16* __restrict__ Xl,
                      const __nv_bfloat16* __restrict__ Wh,
                      const __nv_bfloat16* __restrict__ Wl,
                      const float* __restrict__ bias,
                      float* __restrict__ Y,
                      int M, int N, int K)
{
    extern __shared__ __nv_bfloat16 sm[];
    __shared__ __align__(16) float biasTile[16][136];

    const int tid = threadIdx.x;
    const int wid = tid >> 5;
    const int m0  = blockIdx.y * BM;
    const int n0  = blockIdx.x * BN;
    const int wm  = (wid & 1) * 64;
    const int wn  = (wid >> 1) * 32;

    for (int idx = tid; idx < 16 * 128; idx += 256) {
        int r = idx >> 7;
        int c = idx & 127;
        biasTile[r][c] = bias[n0 + c];
    }
    __syncthreads();

    wmma::fragment<wmma::accumulator, 16, 16, 16, float> acc[4][2];
    for (int mi = 0; mi < 4; mi++)
        for (int ni = 0; ni < 2; ni++)
            wmma::load_matrix_sync(acc[mi][ni], &biasTile[0][wn + ni * 16], 136,
                                   wmma::mem_row_major);

    const int NT = K / BK;

    {
        for (int p = 0; p < 2; p++) {
            int chunk = tid + p * 256;
            int row = chunk >> 2;
            int cc  = chunk & 3;
            const __nv_bfloat16* sa = Xh + (size_t)(m0 + row) * K + cc * 8;
            const __nv_bfloat16* sb = Xl + (size_t)(m0 + row) * K + cc * 8;
            const __nv_bfloat16* sc = Wh + (size_t)(n0 + row) * K + cc * 8;
            const __nv_bfloat16* sd = Wl + (size_t)(n0 + row) * K + cc * 8;
            int so = row * LDT + cc * 8;
            __pipeline_memcpy_async(&sm[so], sa, 16);
            __pipeline_memcpy_async(&sm[TILE_ELEMS + so], sb, 16);
            __pipeline_memcpy_async(&sm[2 * TILE_ELEMS + so], sc, 16);
            __pipeline_memcpy_async(&sm[3 * TILE_ELEMS + so], sd, 16);
        }
        __pipeline_commit();
    }

    for (int t = 0; t < NT; t++) {
        int st = (t & 1) * STAGE_ELEMS;
        if (t + 1 < NT) {
            int k0 = (t + 1) * BK;
            int sn = ((t + 1) & 1) * STAGE_ELEMS;
            for (int p = 0; p < 2; p++) {
                int chunk = tid + p * 256;
                int row = chunk >> 2;
                int cc  = chunk & 3;
                const __nv_bfloat16* sa = Xh + (size_t)(m0 + row) * K + k0 + cc * 8;
                const __nv_bfloat16* sb = Xl + (size_t)(m0 + row) * K + k0 + cc * 8;
                const __nv_bfloat16* sc = Wh + (size_t)(n0 + row) * K + k0 + cc * 8;
                const __nv_bfloat16* sd = Wl + (size_t)(n0 + row) * K + k0 + cc * 8;
                int so = row * LDT + cc * 8;
                __pipeline_memcpy_async(&sm[sn + so], sa, 16);
                __pipeline_memcpy_async(&sm[sn + TILE_ELEMS + so], sb, 16);
                __pipeline_memcpy_async(&sm[sn + 2 * TILE_ELEMS + so], sc, 16);
                __pipeline_memcpy_async(&sm[sn + 3 * TILE_ELEMS + so], sd, 16);
            }
            __pipeline_commit();
            __pipeline_wait_prior(1);
        } else {
            __pipeline_wait_prior(0);
        }
        __syncthreads();

        for (int ks = 0; ks < 2; ks++) {
            int kc = ks * 16;
            wmma::fragment<wmma::matrix_a, 16, 16, 16, __nv_bfloat16, wmma::row_major> ah[4], al[4];
            wmma::fragment<wmma::matrix_b, 16, 16, 16, __nv_bfloat16, wmma::col_major> bh[2], bl[2];
            for (int mi = 0; mi < 4; mi++) {
                int r = wm + mi * 16;
                wmma::load_matrix_sync(ah[mi], &sm[st + r * LDT + kc], LDT);
                wmma::load_matrix_sync(al[mi], &sm[st + TILE_ELEMS + r * LDT + kc], LDT);
            }
            for (int ni = 0; ni < 2; ni++) {
                int r = wn + ni * 16;
                wmma::load_matrix_sync(bh[ni], &sm[st + 2 * TILE_ELEMS + r * LDT + kc], LDT);
                wmma::load_matrix_sync(bl[ni], &sm[st + 3 * TILE_ELEMS + r * LDT + kc], LDT);
            }
            for (int mi = 0; mi < 4; mi++) {
                for (int ni = 0; ni < 2; ni++) {
                    wmma::mma_sync(acc[mi][ni], ah[mi], bh[ni], acc[mi][ni]);
                    wmma::mma_sync(acc[mi][ni], ah[mi], bl[ni], acc[mi][ni]);
                    wmma::mma_sync(acc[mi][ni], al[mi], bh[ni], acc[mi][ni]);
                }
            }
        }
        __syncthreads();
    }

    for (int mi = 0; mi < 4; mi++) {
        for (int ni = 0; ni < 2; ni++) {
            int row = m0 + wm + mi * 16;
            int col = n0 + wn + ni * 16;
            wmma::store_matrix_sync(&Y[(size_t)row * N + col], acc[mi][ni], N,
                                    wmma::mem_row_major);
        }
    }
}

// ---------------------------------------------------------------------------
// Flash attention via wmma (causal), hi/lo bf16 3-pass for QK^T and PV.
// CTA: 64 queries x 1 head, 256 threads (8 warps). K/V double-buffered.
// ---------------------------------------------------------------------------
__device__ __forceinline__ void flash_load_tile(char* dst,
                                                const __nv_bfloat16* src,
                                                int growbase, int h, int tid)
{
    for (int p = 0; p < 2; p++) {
        int idx = tid + p * 256;     // 0..511
        int r = idx >> 3;            // 0..63
        int c = idx & 7;             // 16B chunk
        const __nv_bfloat16* s = src + (size_t)(growbase + r) * D_ + h * DK_ + c * 8;
        __pipeline_memcpy_async(dst + r * 144 + c * 16, s, 16);
    }
}

__global__ __launch_bounds__(256)
void flash_wmma_kernel(const __nv_bfloat16* __restrict__ Qh_g,
                       const __nv_bfloat16* __restrict__ Ql_g,
                       const __nv_bfloat16* __restrict__ Kh_g,
                       const __nv_bfloat16* __restrict__ Kl_g,
                       const __nv_bfloat16* __restrict__ Vh_g,
                       const __nv_bfloat16* __restrict__ Vl_g,
                       float* __restrict__ O)
{
    extern __shared__ char smb[];

    const int tid = threadIdx.x;
    const int wid = tid >> 5;
    const int qt  = blockIdx.x;          // 0..31
    const int bh  = blockIdx.y;          // 0..31
    const int b   = bh / H_;
    const int h   = bh % H_;
    const int q0  = qt * 64;
    const int qrowg = b * S_ + q0;

    float* Sbuf  = (float*)(smb + FS);
    float* Otmp  = (float*)(smb + FOT);
    float* Oacc  = (float*)(smb + FOA);
    float* mArr  = (float*)(smb + FST);
    float* lArr  = mArr + 64;

    // Issue Q (hi/lo) and KV tile 0 — one commit group.
    flash_load_tile(smb + FQH, Qh_g, qrowg, h, tid);
    flash_load_tile(smb + FQL, Ql_g, qrowg, h, tid);
    {
        char* kv = smb + FKV0;
        flash_load_tile(kv,         Kh_g, b * S_, h, tid);
        flash_load_tile(kv + 9216,  Kl_g, b * S_, h, tid);
        flash_load_tile(kv + 18432, Vh_g, b * S_, h, tid);
        flash_load_tile(kv + 27648, Vl_g, b * S_, h, tid);
    }
    __pipeline_commit();

    for (int idx = tid; idx < 64 * 68; idx += 256) Oacc[idx] = 0.f;
    if (tid < 64) {
        mArr[tid] = -INFINITY;
        lArr[tid] = 0.f;
    }

    const int r   = tid >> 2;           // softmax row 0..63
    const int sub = tid & 3;
    const int cb  = sub * 16;
    const int wq  = (wid & 3) * 16;     // warp q-row base
    const int wn2 = (wid >> 2) * 32;    // warp col base (keys for QK, dims for PV)

    for (int kt = 0; kt <= qt; kt++) {
        if (kt < qt) {
            char* kv = smb + (((kt + 1) & 1) ? FKV1 : FKV0);
            int kb2 = b * S_ + (kt + 1) * 64;
            flash_load_tile(kv,         Kh_g, kb2, h, tid);
            flash_load_tile(kv + 9216,  Kl_g, kb2, h, tid);
            flash_load_tile(kv + 18432, Vh_g, kb2, h, tid);
            flash_load_tile(kv + 27648, Vl_g, kb2, h, tid);
            __pipeline_commit();
            __pipeline_wait_prior(1);
        } else {
            __pipeline_wait_prior(0);
        }
        __syncthreads();

        const char* kv = smb + ((kt & 1) ? FKV1 : FKV0);
        const __nv_bfloat16* Khs = (const __nv_bfloat16*)kv;
        const __nv_bfloat16* Kls = (const __nv_bfloat16*)(kv + 9216);
        const __nv_bfloat16* Vhs = (const __nv_bfloat16*)(kv + 18432);
        const __nv_bfloat16* Vls = (const __nv_bfloat16*)(kv + 27648);
        const __nv_bfloat16* Qhs = (const __nv_bfloat16*)(smb + FQH);
        const __nv_bfloat16* Qls = (const __nv_bfloat16*)(smb + FQL);

        // ---- S = Q K^T (3-pass) ----
        {
            wmma::fragment<wmma::accumulator, 16, 16, 16, float> s0, s1;
            wmma::fill_fragment(s0, 0.f);
            wmma::fill_fragment(s1, 0.f);
            for (int ks = 0; ks < 4; ks++) {
                int kc = ks * 16;
                wmma::fragment<wmma::matrix_a, 16, 16, 16, __nv_bfloat16, wmma::row_major> qh, ql;
                wmma::fragment<wmma::matrix_b, 16, 16, 16, __nv_bfloat16, wmma::col_major> kh0, kh1, kl0, kl1;
                wmma::load_matrix_sync(qh, Qhs + wq * 72 + kc, 72);
                wmma::load_matrix_sync(ql, Qls + wq * 72 + kc, 72);
                wmma::load_matrix_sync(kh0, Khs + (wn2 + 0) * 72 + kc, 72);
                wmma::load_matrix_sync(kh1, Khs + (wn2 + 16) * 72 + kc, 72);
                wmma::load_matrix_sync(kl0, Kls + (wn2 + 0) * 72 + kc, 72);
                wmma::load_matrix_sync(kl1, Kls + (wn2 + 16) * 72 + kc, 72);
                wmma::mma_sync(s0, qh, kh0, s0);
                wmma::mma_sync(s0, qh, kl0, s0);
                wmma::mma_sync(s0, ql, kh0, s0);
                wmma::mma_sync(s1, qh, kh1, s1);
                wmma::mma_sync(s1, qh, kl1, s1);
                wmma::mma_sync(s1, ql, kh1, s1);
            }
            wmma::store_matrix_sync(Sbuf + wq * 72 + wn2, s0, 72, wmma::mem_row_major);
            wmma::store_matrix_sync(Sbuf + wq * 72 + wn2 + 16, s1, 72, wmma::mem_row_major);
        }
        __syncthreads();

        // ---- online softmax on rows (4 threads per row) ----
        float sc;
        {
            const int kb = kt * 64;
            float vals[16];
            float mx = -INFINITY;
            const float* Srow = Sbuf + r * 72 + cb;
            for (int i = 0; i < 16; i++) {
                float v = Srow[i] * 0.125f;
                if (kb + cb + i > q0 + r) v = -1e9f;
                vals[i] = v;
                mx = fmaxf(mx, v);
            }
            mx = fmaxf(mx, __shfl_xor_sync(0xffffffffu, mx, 1));
            mx = fmaxf(mx, __shfl_xor_sync(0xffffffffu, mx, 2));
            float mold = mArr[r];
            float mnew = fmaxf(mold, mx);
            float sum = 0.f;
            __nv_bfloat16* Phs = (__nv_bfloat16*)(smb + FPH);
            __nv_bfloat16* Pls = (__nv_bfloat16*)(smb + FPL);
            for (int i = 0; i < 16; i += 2) {
                float p0 = __expf(vals[i] - mnew);
                float p1 = __expf(vals[i + 1] - mnew);
                sum += p0 + p1;
                __nv_bfloat16 h0 = __float2bfloat16(p0);
                __nv_bfloat16 h1 = __float2bfloat16(p1);
                __nv_bfloat162 hh, ll;
                hh.x = h0; hh.y = h1;
                ll.x = __float2bfloat16(p0 - __bfloat162float(h0));
                ll.y = __float2bfloat16(p1 - __bfloat162float(h1));
                *(__nv_bfloat162*)&Phs[r * 72 + cb + i] = hh;
                *(__nv_bfloat162*)&Pls[r * 72 + cb + i] = ll;
            }
            sum += __shfl_xor_sync(0xffffffffu, sum, 1);
            sum += __shfl_xor_sync(0xffffffffu, sum, 2);
            sc = __expf(mold - mnew);
            if (sub == 0) {
                mArr[r] = mnew;
                lArr[r] = lArr[r] * sc + sum;
            }
        }
        __syncthreads();

        // ---- Otile = P V (3-pass) ----
        {
            const __nv_bfloat16* Phs = (const __nv_bfloat16*)(smb + FPH);
            const __nv_bfloat16* Pls = (const __nv_bfloat16*)(smb + FPL);
            wmma::fragment<wmma::accumulator, 16, 16, 16, float> o0, o1;
            wmma::fill_fragment(o0, 0.f);
            wmma::fill_fragment(o1, 0.f);
            for (int ks = 0; ks < 4; ks++) {
                int kc = ks * 16;
                wmma::fragment<wmma::matrix_a, 16, 16, 16, __nv_bfloat16, wmma::row_major> ph, pl;
                wmma::fragment<wmma::matrix_b, 16, 16, 16, __nv_bfloat16, wmma::row_major> vh0, vh1, vl0, vl1;
                wmma::load_matrix_sync(ph, Phs + wq * 72 + kc, 72);
                wmma::load_matrix_sync(pl, Pls + wq * 72 + kc, 72);
                wmma::load_matrix_sync(vh0, Vhs + kc * 72 + wn2, 72);
                wmma::load_matrix_sync(vh1, Vhs + kc * 72 + wn2 + 16, 72);
                wmma::load_matrix_sync(vl0, Vls + kc * 72 + wn2, 72);
                wmma::load_matrix_sync(vl1, Vls + kc * 72 + wn2 + 16, 72);
                wmma::mma_sync(o0, ph, vh0, o0);
                wmma::mma_sync(o0, ph, vl0, o0);
                wmma::mma_sync(o0, pl, vh0, o0);
                wmma::mma_sync(o1, ph, vh1, o1);
                wmma::mma_sync(o1, ph, vl1, o1);
                wmma::mma_sync(o1, pl, vh1, o1);
            }
            wmma::store_matrix_sync(Otmp + wq * 72 + wn2, o0, 72, wmma::mem_row_major);
            wmma::store_matrix_sync(Otmp + wq * 72 + wn2 + 16, o1, 72, wmma::mem_row_major);
        }
        __syncthreads();

        // ---- O rescale-accumulate ----
        for (int i = 0; i < 16; i += 4) {
            float4 oa = *(float4*)&Oacc[r * 68 + cb + i];
            float4 ot = *(float4*)&Otmp[r * 72 + cb + i];
            oa.x = oa.x * sc + ot.x;
            oa.y = oa.y * sc + ot.y;
            oa.z = oa.z * sc + ot.z;
            oa.w = oa.w * sc + ot.w;
            *(float4*)&Oacc[r * 68 + cb + i] = oa;
        }
        __syncthreads();
    }

    // Epilogue: normalize and write this head's slice.
    const float inv = 1.f / lArr[r];
    float* orow = &O[(size_t)(b * S_ + q0 + r) * D_ + h * DK_ + cb];
    for (int i = 0; i < 16; i += 4) {
        float4 oa = *(float4*)&Oacc[r * 68 + cb + i];
        oa.x *= inv; oa.y *= inv; oa.z *= inv; oa.w *= inv;
        *(float4*)&orow[i] = oa;
    }
}

// ---------------------------------------------------------------------------
// Launch. Inputs: q,k,v,mask,Wq,bq,Wk,bk,Wv,bv,Wo,bo
// ---------------------------------------------------------------------------
extern "C" void kernel_launch(void* const* d_in, const int* in_sizes, int n_in,
                              void* d_out, int out_size)
{
    const float* q    = (const float*)d_in[0];
    const float* k    = (const float*)d_in[1];
    const float* v    = (const float*)d_in[2];
    const float* Wq   = (const float*)d_in[4];
    const float* bq   = (const float*)d_in[5];
    const float* Wk   = (const float*)d_in[6];
    const float* bk   = (const float*)d_in[7];
    const float* Wv   = (const float*)d_in[8];
    const float* bv   = (const float*)d_in[9];
    const float* Wo   = (const float*)d_in[10];
    const float* bo   = (const float*)d_in[11];
    float* out = (float*)d_out;

    float *Qp; float *Kp; float *Vp; float *O;
    __nv_bfloat16 *Xh; __nv_bfloat16 *Xl; __nv_bfloat16 *Wh; __nv_bfloat16 *Wl;
    __nv_bfloat16 *Qh; __nv_bfloat16 *Ql; __nv_bfloat16 *Kh; __nv_bfloat16 *Kl;
    __nv_bfloat16 *Vh; __nv_bfloat16 *Vl;
    cudaGetSymbolAddress((void**)&Qp, g_Qp);
    cudaGetSymbolAddress((void**)&Kp, g_Kp);
    cudaGetSymbolAddress((void**)&Vp, g_Vp);
    cudaGetSymbolAddress((void**)&O,  g_O);
    cudaGetSymbolAddress((void**)&Xh, g_Xh);
    cudaGetSymbolAddress((void**)&Xl, g_Xl);
    cudaGetSymbolAddress((void**)&Wh, g_Wh);
    cudaGetSymbolAddress((void**)&Wl, g_Wl);
    cudaGetSymbolAddress((void**)&Qh, g_Qh);
    cudaGetSymbolAddress((void**)&Ql, g_Ql);
    cudaGetSymbolAddress((void**)&Kh, g_Kh);
    cudaGetSymbolAddress((void**)&Kl, g_Kl);
    cudaGetSymbolAddress((void**)&Vh, g_Vh);
    cudaGetSymbolAddress((void**)&Vl, g_Vl);

    cudaFuncSetAttribute(gemm_wmma_kernel,
                         cudaFuncAttributeMaxDynamicSharedMemorySize, SMEM_BYTES);
    cudaFuncSetAttribute(flash_wmma_kernel,
                         cudaFuncAttributeMaxDynamicSharedMemorySize, FLASH_SMEM);

    const int nX4 = M_ * D_ / 4;
    const int nW4 = D_ * D_ / 4;
    dim3 cvtg((nX4 + nW4 + 255) / 256);
    dim3 cvt3g((3 * nX4 + 255) / 256);
    dim3 ggrid(D_ / BN, M_ / BM);

    // Projections
    cvt_merged_kernel<<<cvtg, 256>>>((const float4*)q, Xh, Xl, nX4,
                                     (const float4*)Wq, Wh, Wl, nW4);
    gemm_wmma_kernel<<<ggrid, 256, SMEM_BYTES>>>(Xh, Xl, Wh, Wl, bq, Qp, M_, D_, D_);
    cvt_merged_kernel<<<cvtg, 256>>>((const float4*)k, Xh, Xl, nX4,
                                     (const float4*)Wk, Wh, Wl, nW4);
    gemm_wmma_kernel<<<ggrid, 256, SMEM_BYTES>>>(Xh, Xl, Wh, Wl, bk, Kp, M_, D_, D_);
    cvt_merged_kernel<<<cvtg, 256>>>((const float4*)v, Xh, Xl, nX4,
                                     (const float4*)Wv, Wh, Wl, nW4);
    gemm_wmma_kernel<<<ggrid, 256, SMEM_BYTES>>>(Xh, Xl, Wh, Wl, bv, Vp, M_, D_, D_);

    // Split Q/K/V to bf16 hi/lo for tensor-core flash
    cvt3_kernel<<<cvt3g, 256>>>((const float4*)Qp, Qh, Ql,
                                (const float4*)Kp, Kh, Kl,
                                (const float4*)Vp, Vh, Vl, nX4);

    // Attention (tensor-core)
    dim3 fgrid(S_ / 64, B_ * H_);   // (32, 32)
    flash_wmma_kernel<<<fgrid, 256, FLASH_SMEM>>>(Qh, Ql, Kh, Kl, Vh, Vl, O);

    // Output projection
    cvt_merged_kernel<<<cvtg, 256>>>((const float4*)O, Xh, Xl, nX4,
                                     (const float4*)Wo, Wh, Wl, nW4);
    gemm_wmma_kernel<<<ggrid, 256, SMEM_BYTES>>>(Xh, Xl, Wh, Wl, bo, out, M_, D_, D_);
}